// round 11
// baseline (speedup 1.0000x reference)
#include <cuda_runtime.h>
#include <cstdint>

#define NU 50000
#define NI 50000
#define FH 128
#define EC 800000
#define GC 512
#define CC 16
#define LC 3
#define BN_EPS 1e-5f
#define DEGCAP 96
#define NT 391

#define NODEF (50000ull * 128ull)
#define OFF_XU 0ull
#define OFF_XI (1ull * NODEF)
#define OFF_AGU (2ull * NODEF)
#define OFF_AGI (3ull * NODEF)
#define OFF_NWU (4ull * NODEF)
#define OFF_NWI (5ull * NODEF)
#define OFF_CNT (6ull * NODEF)
#define OFF_INV (OFF_CNT + 512ull)
#define OFF_STATS (OFF_INV + 512ull)
#define OFF_BN (OFF_STATS + 512ull)
#define BUF_TOTAL (OFF_BN + 512ull)

__device__ float g_buf[BUF_TOTAL];
__device__ int g_deg[2 * 50000];
__device__ int g_csr[2ull * 50000ull * DEGCAP];
__device__ unsigned g_ctr_stats;
__device__ unsigned g_ctr_cnt;

// ---------------- helpers ----------------
__device__ __forceinline__ uint32_t smem_u32(const void* p) {
    uint32_t a;
    asm("{ .reg .u64 t; cvta.to.shared.u64 t, %1; cvt.u32.u64 %0, t; }" : "=r"(a) : "l"(p));
    return a;
}
__device__ __forceinline__ float to_tf32(float x) {
    uint32_t r;
    asm("cvt.rn.tf32.f32 %0, %1;" : "=r"(r) : "f"(x));
    return __uint_as_float(r);
}
__device__ __forceinline__ void red_add_v4(float* a, float4 v) {
    asm volatile("red.global.add.v4.f32 [%0], {%1,%2,%3,%4};"
                 :: "l"(a), "f"(v.x), "f"(v.y), "f"(v.z), "f"(v.w) : "memory");
}
__device__ __forceinline__ void mma_tf32(float* c, const uint32_t* a,
                                         uint32_t b0, uint32_t b1) {
    asm volatile(
        "mma.sync.aligned.m16n8k8.row.col.f32.tf32.tf32.f32 "
        "{%0,%1,%2,%3}, {%4,%5,%6,%7}, {%8,%9}, {%0,%1,%2,%3};"
        : "+f"(c[0]), "+f"(c[1]), "+f"(c[2]), "+f"(c[3])
        : "r"(a[0]), "r"(a[1]), "r"(a[2]), "r"(a[3]), "r"(b0), "r"(b1));
}
__device__ __forceinline__ void cp16(uint32_t s, const float* g, int sz) {
    asm volatile("cp.async.ca.shared.global [%0], [%1], 16, %2;"
                 :: "r"(s), "l"(g), "r"(sz) : "memory");
}
#define CP_COMMIT() asm volatile("cp.async.commit_group;" ::: "memory")

// ---------------- setup kernels ----------------
__global__ void k_zeroall(float* __restrict__ degf, float* __restrict__ out,
                          int out4, float* __restrict__ cnt,
                          const float* __restrict__ xu, const float* __restrict__ xi,
                          float* __restrict__ XU, float* __restrict__ XI) {
    int t = blockIdx.x * blockDim.x + threadIdx.x;
    if (t < 25000) {
        reinterpret_cast<float4*>(degf)[t] = make_float4(0.f, 0.f, 0.f, 0.f);
    } else if (t < 25000 + out4) {
        reinterpret_cast<float4*>(out)[t - 25000] = make_float4(0.f, 0.f, 0.f, 0.f);
    } else if (t < 25000 + out4 + 128) {
        reinterpret_cast<float4*>(cnt)[t - 25000 - out4] = make_float4(0.f, 0.f, 0.f, 0.f);
    } else {
        int q = t - (25000 + out4 + 128);
        if (q < 3200000) {
            const float* s;
            float* d;
            if (q < 1600000) { s = xu; d = XU; } else { s = xi; d = XI; q -= 1600000; }
            float4 v = reinterpret_cast<const float4*>(s)[q];
            reinterpret_cast<float4*>(d)[q] =
                make_float4(to_tf32(v.x), to_tf32(v.y), to_tf32(v.z), to_tf32(v.w));
        }
    }
}

__global__ void k_build2(const int* __restrict__ eu2i, const int* __restrict__ ei2u,
                         int* __restrict__ deg, int* __restrict__ csr) {
    int t = blockIdx.x * blockDim.x + threadIdx.x;
    if (t >= 2 * EC) return;
    const int* edge = (t < EC) ? eu2i : ei2u;
    int e = (t < EC) ? t : t - EC;
    int* dp = (t < EC) ? deg : deg + 50000;
    int* cp = (t < EC) ? csr : csr + 50000ull * DEGCAP;
    int src = edge[e];
    int dst = edge[EC + e];
    int pos = atomicAdd(&dp[dst], 1);
    if (pos < DEGCAP) cp[(size_t)dst * DEGCAP + pos] = src;
}

__global__ void __launch_bounds__(1024) k_count(
    const int* __restrict__ bu, const int* __restrict__ bi,
    float* __restrict__ cnt, float* __restrict__ inv) {
    __shared__ int h[GC];
    for (int i = threadIdx.x; i < GC; i += 1024) h[i] = 0;
    __syncthreads();
    for (int t = blockIdx.x * 1024 + threadIdx.x; t < NU + NI;
         t += gridDim.x * 1024) {
        int b = (t < NU) ? bu[t] : bi[t - NU];
        atomicAdd(&h[b], 1);
    }
    __syncthreads();
    for (int i = threadIdx.x; i < GC; i += 1024)
        if (h[i]) atomicAdd(&cnt[i], (float)h[i]);
    __threadfence();
    __shared__ bool last;
    if (threadIdx.x == 0)
        last = (atomicAdd(&g_ctr_cnt, 1u) == gridDim.x - 1);
    __syncthreads();
    if (last) {
        if (threadIdx.x < GC)
            inv[threadIdx.x] = 1.0f / fmaxf(cnt[threadIdx.x], 1.0f);
        if (threadIdx.x == 0) g_ctr_cnt = 0;
    }
}

// merged gather; writes tf32-rounded agg; block 0 zeroes this layer's stats
__global__ void k_gather(const float* __restrict__ xu, const float* __restrict__ xi,
                         float* __restrict__ aggU, float* __restrict__ aggI,
                         float* __restrict__ stats) {
    if (blockIdx.x == 0 && threadIdx.x < 128) {
#pragma unroll
        for (int i = 0; i < 4; i++) stats[threadIdx.x + i * 128] = 0.f;
    }
    int t = blockIdx.x * blockDim.x + threadIdx.x;
    int gn = t >> 5, lane = t & 31;
    if (gn >= 100000) return;
    const float* x;
    float* dst;
    const int* dp;
    const int* lst;
    int node;
    if (gn < 50000) {
        node = gn; x = xu; dst = aggI; dp = g_deg;
        lst = g_csr + (size_t)node * DEGCAP;
    } else {
        node = gn - 50000; x = xi; dst = aggU; dp = g_deg + 50000;
        lst = g_csr + 50000ull * DEGCAP + (size_t)node * DEGCAP;
    }
    int d = min(dp[node], DEGCAP);
    float ax = 0.f, ay = 0.f, az = 0.f, aw = 0.f;
    int j = 0;
    for (; j + 4 <= d; j += 4) {
        int s0 = lst[j], s1 = lst[j + 1], s2 = lst[j + 2], s3 = lst[j + 3];
        float4 v0 = *reinterpret_cast<const float4*>(&x[(size_t)s0 * FH + lane * 4]);
        float4 v1 = *reinterpret_cast<const float4*>(&x[(size_t)s1 * FH + lane * 4]);
        float4 v2 = *reinterpret_cast<const float4*>(&x[(size_t)s2 * FH + lane * 4]);
        float4 v3 = *reinterpret_cast<const float4*>(&x[(size_t)s3 * FH + lane * 4]);
        ax += v0.x + v1.x + v2.x + v3.x;
        ay += v0.y + v1.y + v2.y + v3.y;
        az += v0.z + v1.z + v2.z + v3.z;
        aw += v0.w + v1.w + v2.w + v3.w;
    }
    for (; j < d; j++) {
        int s = lst[j];
        float4 v = *reinterpret_cast<const float4*>(&x[(size_t)s * FH + lane * 4]);
        ax += v.x; ay += v.y; az += v.z; aw += v.w;
    }
    *reinterpret_cast<float4*>(&dst[(size_t)node * FH + lane * 4]) =
        make_float4(to_tf32(ax), to_tf32(ay), to_tf32(az), to_tf32(aw));
}

// ---------------- mma.sync tf32 GEMM: 3-stage cp.async + fused BN stats ----------------
#define CHF 4608                       // floats per 128x36 operand buffer
#define GSMEM (3 * 2 * CHF * 4)        // 110592 bytes (3 stages x (A+W))

__global__ void __launch_bounds__(256, 2) k_gemm_mma(
    const float* __restrict__ aggI, const float* __restrict__ xI,
    const float* __restrict__ aggU, const float* __restrict__ xU,
    const float* __restrict__ WaI, const float* __restrict__ WbI,
    const float* __restrict__ WaU, const float* __restrict__ WbU,
    const float* __restrict__ bI, const float* __restrict__ bU,
    float* __restrict__ nI, float* __restrict__ nU,
    float* __restrict__ stats, float* __restrict__ bn,
    const float* __restrict__ gu, const float* __restrict__ bu_,
    const float* __restrict__ gi, const float* __restrict__ bi_) {
    extern __shared__ float sm[];
    int tid = threadIdx.x, wid = tid >> 5, lane = tid & 31;
    bool item = blockIdx.x < NT;
    int tile = item ? blockIdx.x : blockIdx.x - NT;
    const float* A0 = item ? aggI : aggU;
    const float* A1 = item ? xI : xU;
    const float* Wa = item ? WaI : WaU;
    const float* Wb = item ? WbI : WbU;
    const float* bias = item ? bI : bU;
    float* outp = item ? nI : nU;
    int row0 = tile * 128;

    int g = lane >> 2, q = lane & 3;
    int wm = wid & 3, wn = wid >> 2;
    uint32_t sbase = smem_u32(sm);

    float c[2][8][4];
#pragma unroll
    for (int mt = 0; mt < 2; mt++)
#pragma unroll
        for (int nt = 0; nt < 8; nt++)
#pragma unroll
            for (int e = 0; e < 4; e++) c[mt][nt][e] = 0.f;

    // stage chunk ch into ring buffer ch%3 (A at +0, W at +CHF floats)
    auto stage = [&](int ch) {
        const float* Ap = (ch < 4) ? A0 : A1;
        const float* Wp = (ch < 4) ? Wa : Wb;
        int f0 = (ch & 3) * 32;
        uint32_t bo = sbase + (uint32_t)((ch % 3) * 2 * CHF) * 4;
#pragma unroll
        for (int i = 0; i < 4; i++) {
            int idx = i * 256 + tid;       // 0..1023
            int r = idx >> 3, j = idx & 7;
            int gr = row0 + r;
            int sz = (gr < 50000) ? 16 : 0;
            int grc = min(gr, 49999);
            cp16(bo + (r * 36 + j * 4) * 4, Ap + (size_t)grc * FH + f0 + j * 4, sz);
            cp16(bo + (CHF + r * 36 + j * 4) * 4, Wp + r * FH + f0 + j * 4, 16);
        }
    };

    stage(0); CP_COMMIT();
    stage(1); CP_COMMIT();

#pragma unroll 1
    for (int ch = 0; ch < 8; ch++) {
        if (ch < 7) asm volatile("cp.async.wait_group 1;" ::: "memory");
        else        asm volatile("cp.async.wait_group 0;" ::: "memory");
        __syncthreads();

        // stage 2-ahead into the buffer nobody reads this or next iteration
        if (ch < 6) { stage(ch + 2); CP_COMMIT(); }

        const float* sA = sm + (ch % 3) * 2 * CHF;
        const float* sW = sA + CHF;

#pragma unroll
        for (int s = 0; s < 4; s++) {
            int k0 = s * 8;
            uint32_t a[2][4];
#pragma unroll
            for (int mt = 0; mt < 2; mt++) {
                int m0 = wm * 32 + mt * 16;
                a[mt][0] = __float_as_uint(sA[(m0 + g) * 36 + k0 + q]);
                a[mt][1] = __float_as_uint(sA[(m0 + g + 8) * 36 + k0 + q]);
                a[mt][2] = __float_as_uint(sA[(m0 + g) * 36 + k0 + q + 4]);
                a[mt][3] = __float_as_uint(sA[(m0 + g + 8) * 36 + k0 + q + 4]);
            }
#pragma unroll
            for (int nt = 0; nt < 8; nt++) {
                int n0 = wn * 64 + nt * 8;
                uint32_t b0 = __float_as_uint(sW[(n0 + g) * 36 + k0 + q]);
                uint32_t b1 = __float_as_uint(sW[(n0 + g) * 36 + k0 + q + 4]);
                mma_tf32(c[0][nt], a[0], b0, b1);
                mma_tf32(c[1][nt], a[1], b0, b1);
            }
        }
        // no trailing barrier: next iteration's wait+syncthreads protects the ring
    }

    // ---- epilogue: bias add + store + shuffle-reduced BN stats ----
    float* sg = item ? stats + 256 : stats;   // [h]=sum, [h+128]=sumsq
#pragma unroll
    for (int nt = 0; nt < 8; nt++) {
        int n0 = wn * 64 + nt * 8 + 2 * q;
        float2 bb = *reinterpret_cast<const float2*>(&bias[n0]);
        float s0 = 0.f, q0 = 0.f, s1 = 0.f, q1 = 0.f;
#pragma unroll
        for (int mt = 0; mt < 2; mt++) {
            int r = row0 + wm * 32 + mt * 16 + g;
            if (r < 50000) {
                float ox = c[mt][nt][0] + bb.x;
                float oy = c[mt][nt][1] + bb.y;
                *reinterpret_cast<float2*>(&outp[(size_t)r * FH + n0]) =
                    make_float2(ox, oy);
                float vx = fmaxf(ox, 0.f), vy = fmaxf(oy, 0.f);
                s0 += vx; q0 += vx * vx; s1 += vy; q1 += vy * vy;
            }
            if (r + 8 < 50000) {
                float ox = c[mt][nt][2] + bb.x;
                float oy = c[mt][nt][3] + bb.y;
                *reinterpret_cast<float2*>(&outp[(size_t)(r + 8) * FH + n0]) =
                    make_float2(ox, oy);
                float vx = fmaxf(ox, 0.f), vy = fmaxf(oy, 0.f);
                s0 += vx; q0 += vx * vx; s1 += vy; q1 += vy * vy;
            }
        }
        // reduce over the 8 lanes sharing this column (xor over g bits 2..4)
#pragma unroll
        for (int off = 4; off < 32; off <<= 1) {
            s0 += __shfl_xor_sync(0xFFFFFFFFu, s0, off);
            q0 += __shfl_xor_sync(0xFFFFFFFFu, q0, off);
            s1 += __shfl_xor_sync(0xFFFFFFFFu, s1, off);
            q1 += __shfl_xor_sync(0xFFFFFFFFu, q1, off);
        }
        if (g == 0) {
            atomicAdd(&sg[n0], s0);
            atomicAdd(&sg[n0 + 128], q0);
            atomicAdd(&sg[n0 + 1], s1);
            atomicAdd(&sg[n0 + 1 + 128], q1);
        }
    }

    // last block computes BN scale/shift for both sides
    __threadfence();
    __shared__ bool lastb;
    if (tid == 0)
        lastb = (atomicAdd(&g_ctr_stats, 1u) == 2 * NT - 1);
    __syncthreads();
    if (lastb) {
        if (tid < 256) {
            int hh = tid & 127;
            const float* ss = (tid < 128) ? stats : stats + 256;
            const float* gg = (tid < 128) ? gu : gi;
            const float* be = (tid < 128) ? bu_ : bi_;
            float* o = (tid < 128) ? bn : bn + 256;
            float invn = 1.0f / 50000.0f;
            float m = ss[hh] * invn;
            float var = ss[hh + 128] * invn - m * m;
            float sc = gg[hh] * rsqrtf(var + BN_EPS);
            o[hh] = sc;
            o[hh + 128] = be[hh] - m * sc;
        }
        if (tid == 0) g_ctr_stats = 0;
    }
}

// apply relu+BN; write tf32-rounded next features; accumulate pooled (exact)
__global__ void k_apply(const float* __restrict__ nu_, const float* __restrict__ ni_,
                        const float* __restrict__ bn, const int* __restrict__ bu,
                        const int* __restrict__ bi, const float* __restrict__ inv,
                        float* __restrict__ XU, float* __restrict__ XI,
                        float* __restrict__ pooled) {
    int t = blockIdx.x * blockDim.x + threadIdx.x;
    if (t >= (NU + NI) * 32) return;
    int gn = t >> 5, lane = t & 31;
    const float* v;
    const float* sc;
    const int* bt;
    float* xo;
    int r;
    if (gn < NU) { v = nu_; sc = bn; bt = bu; xo = XU; r = gn; }
    else { v = ni_; sc = bn + 256; bt = bi; xo = XI; r = gn - NU; }
    int g = bt[r];
    float ic = inv[g];
    float4 x = *reinterpret_cast<const float4*>(&v[(size_t)r * FH + lane * 4]);
    float4 s4 = *reinterpret_cast<const float4*>(&sc[lane * 4]);
    float4 h4 = *reinterpret_cast<const float4*>(&sc[128 + lane * 4]);
    float4 y;
    y.x = fmaxf(x.x, 0.f) * s4.x + h4.x;
    y.y = fmaxf(x.y, 0.f) * s4.y + h4.y;
    y.z = fmaxf(x.z, 0.f) * s4.z + h4.z;
    y.w = fmaxf(x.w, 0.f) * s4.w + h4.w;
    *reinterpret_cast<float4*>(&xo[(size_t)r * FH + lane * 4]) =
        make_float4(to_tf32(y.x), to_tf32(y.y), to_tf32(y.z), to_tf32(y.w));
    red_add_v4(&pooled[(size_t)g * FH + lane * 4],
               make_float4(y.x * ic, y.y * ic, y.z * ic, y.w * ic));
}

__global__ void k_logits(const float* __restrict__ feats, const float* __restrict__ fcW,
                         const float* __restrict__ fcb, float* __restrict__ out) {
    int lg = blockIdx.x;
    int l = lg / GC;
    __shared__ float sf[FH];
    sf[threadIdx.x] = feats[(size_t)lg * FH + threadIdx.x];
    __syncthreads();
    int c = threadIdx.x;
    if (c < CC) {
        const float* w = &fcW[(size_t)(l * CC + c) * FH];
        float a = fcb[l * CC + c];
#pragma unroll 8
        for (int h = 0; h < FH; h++) a += sf[h] * w[h];
        out[(size_t)lg * CC + c] = a;
    }
}

// ---------------------------------------------------------------------------
extern "C" void kernel_launch(void* const* d_in, const int* in_sizes, int n_in,
                              void* d_out, int out_size) {
    const float* x_user    = (const float*)d_in[0];
    const float* x_item    = (const float*)d_in[1];
    const int*   e_u2i     = (const int*)d_in[2];
    const int*   e_i2u     = (const int*)d_in[3];
    const int*   b_user    = (const int*)d_in[4];
    const int*   b_item    = (const int*)d_in[5];
    const float* Wrel_u2i  = (const float*)d_in[6];
    const float* Wroot_u2i = (const float*)d_in[7];
    const float* bias_u2i  = (const float*)d_in[8];
    const float* Wrel_i2u  = (const float*)d_in[9];
    const float* Wroot_i2u = (const float*)d_in[10];
    const float* bias_i2u  = (const float*)d_in[11];
    const float* bng_u     = (const float*)d_in[12];
    const float* bnb_u     = (const float*)d_in[13];
    const float* bng_i     = (const float*)d_in[14];
    const float* bnb_i     = (const float*)d_in[15];
    const float* fcW       = (const float*)d_in[16];
    const float* fcb       = (const float*)d_in[17];
    float* out = (float*)d_out;

    float* buf = nullptr;
    cudaGetSymbolAddress((void**)&buf, g_buf);
    int* deg = nullptr;
    cudaGetSymbolAddress((void**)&deg, g_deg);
    int* csr = nullptr;
    cudaGetSymbolAddress((void**)&csr, g_csr);

    cudaFuncSetAttribute(k_gemm_mma, cudaFuncAttributeMaxDynamicSharedMemorySize, GSMEM);

    float* XU    = buf + OFF_XU;
    float* XI    = buf + OFF_XI;
    float* agg_u = buf + OFF_AGU;
    float* agg_i = buf + OFF_AGI;
    float* new_u = buf + OFF_NWU;
    float* new_i = buf + OFF_NWI;
    float* cnt   = buf + OFF_CNT;
    float* inv   = buf + OFF_INV;
    float* stats = buf + OFF_STATS;
    float* bn    = buf + OFF_BN;

    const int OUT_ELEMS = LC * GC * CC + LC * GC * FH;   // 221184
    const int OUT4 = OUT_ELEMS / 4;                      // 55296
    float* feats = out + LC * GC * CC;

    const int ZTOT = 25000 + OUT4 + 128 + 3200000;

    // 0: zero deg/out/cnt + pre-round inputs into XU/XI
    k_zeroall<<<(ZTOT + 255) / 256, 256>>>((float*)deg, out, OUT4, cnt,
                                           x_user, x_item, XU, XI);
    // 1: build both CSR bucket sets
    k_build2<<<(2 * EC + 255) / 256, 256>>>(e_u2i, e_i2u, deg, csr);
    // 2: layer-0 gather (zeroes stats)
    k_gather<<<(100000 * 32 + 255) / 256, 256>>>(x_user, x_item, agg_u, agg_i, stats);
    // 3: layer-0 GEMM + fused BN stats (ncu captures this launch)
    k_gemm_mma<<<2 * NT, 256, GSMEM>>>(agg_i, XI, agg_u, XU,
                                       Wrel_u2i, Wroot_u2i,
                                       Wrel_i2u, Wroot_i2u,
                                       bias_u2i, bias_i2u, new_i, new_u,
                                       stats, bn, bng_u, bnb_u, bng_i, bnb_i);
    // 4: group counts + inverse
    k_count<<<64, 1024>>>(b_user, b_item, cnt, inv);
    // 5: layer-0 apply
    k_apply<<<((NU + NI) * 32 + 255) / 256, 256>>>(new_u, new_i, bn, b_user,
                                                   b_item, inv, XU, XI, feats);

    for (int l = 1; l < LC; l++) {
        k_gather<<<(100000 * 32 + 255) / 256, 256>>>(XU, XI, agg_u, agg_i, stats);
        size_t wo = (size_t)l * FH * FH;
        k_gemm_mma<<<2 * NT, 256, GSMEM>>>(agg_i, XI, agg_u, XU,
                                           Wrel_u2i + wo, Wroot_u2i + wo,
                                           Wrel_i2u + wo, Wroot_i2u + wo,
                                           bias_u2i + l * FH, bias_i2u + l * FH,
                                           new_i, new_u,
                                           stats, bn, bng_u, bnb_u, bng_i, bnb_i);
        float* fl = feats + (size_t)l * GC * FH;
        k_apply<<<((NU + NI) * 32 + 255) / 256, 256>>>(new_u, new_i, bn, b_user,
                                                       b_item, inv, XU, XI, fl);
    }

    k_logits<<<LC * GC, FH>>>(feats, fcW, fcb, out);
}

// round 12
// speedup vs baseline: 1.3104x; 1.3104x over previous
#include <cuda_runtime.h>
#include <cstdint>

#define NU 50000
#define NI 50000
#define FH 128
#define EC 800000
#define GC 512
#define CC 16
#define LC 3
#define BN_EPS 1e-5f
#define DEGCAP 96
#define NT 391

#define NODEF (50000ull * 128ull)
#define OFF_XU 0ull
#define OFF_XI (1ull * NODEF)
#define OFF_AGU (2ull * NODEF)
#define OFF_AGI (3ull * NODEF)
#define OFF_NWU (4ull * NODEF)
#define OFF_NWI (5ull * NODEF)
#define OFF_CNT (6ull * NODEF)
#define OFF_INV (OFF_CNT + 512ull)
#define OFF_STATS (OFF_INV + 512ull)    // [0..255] user, [256..511] item
#define OFF_BN (OFF_STATS + 512ull)     // [0..255] user, [256..511] item
#define BUF_TOTAL (OFF_BN + 512ull)

__device__ float g_buf[BUF_TOTAL];
__device__ int g_deg[2 * 50000];
__device__ int g_csr[2ull * 50000ull * DEGCAP];
__device__ unsigned g_ctr_su;   // per-side stats counters; last block resets
__device__ unsigned g_ctr_si;
__device__ unsigned g_ctr_cnt;

// ---------------- helpers ----------------
__device__ __forceinline__ uint32_t smem_u32(const void* p) {
    uint32_t a;
    asm("{ .reg .u64 t; cvta.to.shared.u64 t, %1; cvt.u32.u64 %0, t; }" : "=r"(a) : "l"(p));
    return a;
}
__device__ __forceinline__ float to_tf32(float x) {
    uint32_t r;
    asm("cvt.rn.tf32.f32 %0, %1;" : "=r"(r) : "f"(x));
    return __uint_as_float(r);
}
__device__ __forceinline__ void red_add_v4(float* a, float4 v) {
    asm volatile("red.global.add.v4.f32 [%0], {%1,%2,%3,%4};"
                 :: "l"(a), "f"(v.x), "f"(v.y), "f"(v.z), "f"(v.w) : "memory");
}
__device__ __forceinline__ void mma_tf32(float* c, const uint32_t* a,
                                         uint32_t b0, uint32_t b1) {
    asm volatile(
        "mma.sync.aligned.m16n8k8.row.col.f32.tf32.tf32.f32 "
        "{%0,%1,%2,%3}, {%4,%5,%6,%7}, {%8,%9}, {%0,%1,%2,%3};"
        : "+f"(c[0]), "+f"(c[1]), "+f"(c[2]), "+f"(c[3])
        : "r"(a[0]), "r"(a[1]), "r"(a[2]), "r"(a[3]), "r"(b0), "r"(b1));
}
__device__ __forceinline__ void cp16(uint32_t s, const float* g, int sz) {
    asm volatile("cp.async.ca.shared.global [%0], [%1], 16, %2;"
                 :: "r"(s), "l"(g), "r"(sz) : "memory");
}
#define CP_COMMIT() asm volatile("cp.async.commit_group;" ::: "memory")

// ---------------- setup kernels ----------------
__global__ void k_zeroall(float* __restrict__ degf, float* __restrict__ out,
                          int out4, float* __restrict__ cnt,
                          const float* __restrict__ xu, const float* __restrict__ xi,
                          float* __restrict__ XU, float* __restrict__ XI) {
    int t = blockIdx.x * blockDim.x + threadIdx.x;
    if (t < 25000) {
        reinterpret_cast<float4*>(degf)[t] = make_float4(0.f, 0.f, 0.f, 0.f);
    } else if (t < 25000 + out4) {
        reinterpret_cast<float4*>(out)[t - 25000] = make_float4(0.f, 0.f, 0.f, 0.f);
    } else if (t < 25000 + out4 + 128) {
        reinterpret_cast<float4*>(cnt)[t - 25000 - out4] = make_float4(0.f, 0.f, 0.f, 0.f);
    } else {
        int q = t - (25000 + out4 + 128);
        if (q < 3200000) {
            const float* s;
            float* d;
            if (q < 1600000) { s = xu; d = XU; } else { s = xi; d = XI; q -= 1600000; }
            float4 v = reinterpret_cast<const float4*>(s)[q];
            reinterpret_cast<float4*>(d)[q] =
                make_float4(to_tf32(v.x), to_tf32(v.y), to_tf32(v.z), to_tf32(v.w));
        }
    }
}

__global__ void k_build2(const int* __restrict__ eu2i, const int* __restrict__ ei2u,
                         int* __restrict__ deg, int* __restrict__ csr) {
    int t = blockIdx.x * blockDim.x + threadIdx.x;
    if (t >= 2 * EC) return;
    const int* edge = (t < EC) ? eu2i : ei2u;
    int e = (t < EC) ? t : t - EC;
    int* dp = (t < EC) ? deg : deg + 50000;
    int* cp = (t < EC) ? csr : csr + 50000ull * DEGCAP;
    int src = edge[e];
    int dst = edge[EC + e];
    int pos = atomicAdd(&dp[dst], 1);
    if (pos < DEGCAP) cp[(size_t)dst * DEGCAP + pos] = src;
}

__global__ void __launch_bounds__(1024) k_count(
    const int* __restrict__ bu, const int* __restrict__ bi,
    float* __restrict__ cnt, float* __restrict__ inv) {
    __shared__ int h[GC];
    for (int i = threadIdx.x; i < GC; i += 1024) h[i] = 0;
    __syncthreads();
    for (int t = blockIdx.x * 1024 + threadIdx.x; t < NU + NI;
         t += gridDim.x * 1024) {
        int b = (t < NU) ? bu[t] : bi[t - NU];
        atomicAdd(&h[b], 1);
    }
    __syncthreads();
    for (int i = threadIdx.x; i < GC; i += 1024)
        if (h[i]) atomicAdd(&cnt[i], (float)h[i]);
    __threadfence();
    __shared__ bool last;
    if (threadIdx.x == 0)
        last = (atomicAdd(&g_ctr_cnt, 1u) == gridDim.x - 1);
    __syncthreads();
    if (last) {
        if (threadIdx.x < GC)
            inv[threadIdx.x] = 1.0f / fmaxf(cnt[threadIdx.x], 1.0f);
        if (threadIdx.x == 0) g_ctr_cnt = 0;
    }
}

// ---------------- per-side gather ----------------
// agg[dst] = sum over csr bucket of x[src]; tf32-rounded output.
// Block 0 zeroes this side's 256-float stats region for the coming layer.
__global__ void k_gather_s(const float* __restrict__ x, float* __restrict__ agg,
                           const int* __restrict__ deg, const int* __restrict__ csr,
                           float* __restrict__ stats_side) {
    if (blockIdx.x == 0 && threadIdx.x < 256) stats_side[threadIdx.x] = 0.f;
    int t = blockIdx.x * blockDim.x + threadIdx.x;
    int node = t >> 5, lane = t & 31;
    if (node >= 50000) return;
    int d = min(deg[node], DEGCAP);
    const int* lst = csr + (size_t)node * DEGCAP;
    float ax = 0.f, ay = 0.f, az = 0.f, aw = 0.f;
    int j = 0;
    for (; j + 4 <= d; j += 4) {
        int s0 = lst[j], s1 = lst[j + 1], s2 = lst[j + 2], s3 = lst[j + 3];
        float4 v0 = *reinterpret_cast<const float4*>(&x[(size_t)s0 * FH + lane * 4]);
        float4 v1 = *reinterpret_cast<const float4*>(&x[(size_t)s1 * FH + lane * 4]);
        float4 v2 = *reinterpret_cast<const float4*>(&x[(size_t)s2 * FH + lane * 4]);
        float4 v3 = *reinterpret_cast<const float4*>(&x[(size_t)s3 * FH + lane * 4]);
        ax += v0.x + v1.x + v2.x + v3.x;
        ay += v0.y + v1.y + v2.y + v3.y;
        az += v0.z + v1.z + v2.z + v3.z;
        aw += v0.w + v1.w + v2.w + v3.w;
    }
    for (; j < d; j++) {
        int s = lst[j];
        float4 v = *reinterpret_cast<const float4*>(&x[(size_t)s * FH + lane * 4]);
        ax += v.x; ay += v.y; az += v.z; aw += v.w;
    }
    *reinterpret_cast<float4*>(&agg[(size_t)node * FH + lane * 4]) =
        make_float4(to_tf32(ax), to_tf32(ay), to_tf32(az), to_tf32(aw));
}

// ---------------- per-side mma.sync tf32 GEMM (R10-proven body) ----------------
#define CHF 4608                       // floats per 128x36 buffer
#define GSMEM (4 * CHF * 4)            // 73728 bytes

__global__ void __launch_bounds__(256, 2) k_gemm_s(
    const float* __restrict__ A0, const float* __restrict__ A1,
    const float* __restrict__ Wa, const float* __restrict__ Wb,
    const float* __restrict__ bias, float* __restrict__ outp) {
    extern __shared__ float sm[];
    int tid = threadIdx.x, wid = tid >> 5, lane = tid & 31;
    int row0 = blockIdx.x * 128;

    int g = lane >> 2, q = lane & 3;
    int wm = wid & 3, wn = wid >> 2;

    uint32_t sA_u = smem_u32(sm);
    uint32_t sW_u = sA_u + 2 * CHF * 4;

    float c[2][8][4];
#pragma unroll
    for (int mt = 0; mt < 2; mt++)
#pragma unroll
        for (int nt = 0; nt < 8; nt++)
#pragma unroll
            for (int e = 0; e < 4; e++) c[mt][nt][e] = 0.f;

    auto stage = [&](int ch, int b) {
        const float* Ap = (ch < 4) ? A0 : A1;
        const float* Wp = (ch < 4) ? Wa : Wb;
        int f0 = (ch & 3) * 32;
        uint32_t ao = sA_u + b * CHF * 4;
        uint32_t wo = sW_u + b * CHF * 4;
#pragma unroll
        for (int i = 0; i < 4; i++) {
            int idx = i * 256 + tid;
            int r = idx >> 3, j = idx & 7;
            int gr = row0 + r;
            int sz = (gr < 50000) ? 16 : 0;
            int grc = min(gr, 49999);
            cp16(ao + (r * 36 + j * 4) * 4, Ap + (size_t)grc * FH + f0 + j * 4, sz);
            cp16(wo + (r * 36 + j * 4) * 4, Wp + r * FH + f0 + j * 4, 16);
        }
    };

    stage(0, 0); CP_COMMIT();
    stage(1, 1); CP_COMMIT();

#pragma unroll 1
    for (int ch = 0; ch < 8; ch++) {
        if (ch < 7) asm volatile("cp.async.wait_group 1;" ::: "memory");
        else        asm volatile("cp.async.wait_group 0;" ::: "memory");
        __syncthreads();

        const float* sA = sm + (ch & 1) * CHF;
        const float* sW = sm + 2 * CHF + (ch & 1) * CHF;

#pragma unroll
        for (int s = 0; s < 4; s++) {
            int k0 = s * 8;
            uint32_t a[2][4];
#pragma unroll
            for (int mt = 0; mt < 2; mt++) {
                int m0 = wm * 32 + mt * 16;
                a[mt][0] = __float_as_uint(sA[(m0 + g) * 36 + k0 + q]);
                a[mt][1] = __float_as_uint(sA[(m0 + g + 8) * 36 + k0 + q]);
                a[mt][2] = __float_as_uint(sA[(m0 + g) * 36 + k0 + q + 4]);
                a[mt][3] = __float_as_uint(sA[(m0 + g + 8) * 36 + k0 + q + 4]);
            }
#pragma unroll
            for (int nt = 0; nt < 8; nt++) {
                int n0 = wn * 64 + nt * 8;
                uint32_t b0 = __float_as_uint(sW[(n0 + g) * 36 + k0 + q]);
                uint32_t b1 = __float_as_uint(sW[(n0 + g) * 36 + k0 + q + 4]);
                mma_tf32(c[0][nt], a[0], b0, b1);
                mma_tf32(c[1][nt], a[1], b0, b1);
            }
        }
        __syncthreads();

        if (ch < 6) { stage(ch + 2, ch & 1); CP_COMMIT(); }
    }

#pragma unroll
    for (int nt = 0; nt < 8; nt++) {
        int n0 = wn * 64 + nt * 8 + 2 * q;
        float2 bb = *reinterpret_cast<const float2*>(&bias[n0]);
#pragma unroll
        for (int mt = 0; mt < 2; mt++) {
            int r = row0 + wm * 32 + mt * 16 + g;
            if (r < 50000) {
                float2 o = make_float2(c[mt][nt][0] + bb.x, c[mt][nt][1] + bb.y);
                *reinterpret_cast<float2*>(&outp[(size_t)r * FH + n0]) = o;
            }
            if (r + 8 < 50000) {
                float2 o = make_float2(c[mt][nt][2] + bb.x, c[mt][nt][3] + bb.y);
                *reinterpret_cast<float2*>(&outp[(size_t)(r + 8) * FH + n0]) = o;
            }
        }
    }
}

// ---------------- per-side BN stats + fused bnparams (last block) ----------------
__global__ void k_stats_s(const float* __restrict__ v, float* __restrict__ stats_side,
                          float* __restrict__ bn_side, const float* __restrict__ gamma,
                          const float* __restrict__ beta, unsigned* __restrict__ ctr) {
    int h = threadIdx.x;
    int r0 = blockIdx.x * 128;
    int re = min(r0 + 128, 50000);
    float a = 0.f, qq = 0.f;
    for (int r = r0; r < re; r++) {
        float x = fmaxf(v[(size_t)r * FH + h], 0.f);
        a += x;
        qq += x * x;
    }
    atomicAdd(&stats_side[h], a);
    atomicAdd(&stats_side[h + 128], qq);

    __threadfence();
    __shared__ bool last;
    if (threadIdx.x == 0)
        last = (atomicAdd(ctr, 1u) == NT - 1);
    __syncthreads();
    if (last) {
        float invn = 1.0f / 50000.0f;
        float m = stats_side[h] * invn;
        float var = stats_side[h + 128] * invn - m * m;
        float sc = gamma[h] * rsqrtf(var + BN_EPS);
        bn_side[h] = sc;
        bn_side[h + 128] = beta[h] - m * sc;
        if (threadIdx.x == 0) *ctr = 0;
    }
}

// ---------------- per-side apply ----------------
__global__ void k_apply_s(const float* __restrict__ v, const float* __restrict__ bn_side,
                          const int* __restrict__ batch, const float* __restrict__ inv,
                          float* __restrict__ xout, float* __restrict__ pooled) {
    int t = blockIdx.x * blockDim.x + threadIdx.x;
    if (t >= 50000 * 32) return;
    int r = t >> 5, lane = t & 31;
    int g = batch[r];
    float ic = inv[g];
    float4 x = *reinterpret_cast<const float4*>(&v[(size_t)r * FH + lane * 4]);
    float4 s4 = *reinterpret_cast<const float4*>(&bn_side[lane * 4]);
    float4 h4 = *reinterpret_cast<const float4*>(&bn_side[128 + lane * 4]);
    float4 y;
    y.x = fmaxf(x.x, 0.f) * s4.x + h4.x;
    y.y = fmaxf(x.y, 0.f) * s4.y + h4.y;
    y.z = fmaxf(x.z, 0.f) * s4.z + h4.z;
    y.w = fmaxf(x.w, 0.f) * s4.w + h4.w;
    *reinterpret_cast<float4*>(&xout[(size_t)r * FH + lane * 4]) =
        make_float4(to_tf32(y.x), to_tf32(y.y), to_tf32(y.z), to_tf32(y.w));
    red_add_v4(&pooled[(size_t)g * FH + lane * 4],
               make_float4(y.x * ic, y.y * ic, y.z * ic, y.w * ic));
}

__global__ void k_logits(const float* __restrict__ feats, const float* __restrict__ fcW,
                         const float* __restrict__ fcb, float* __restrict__ out) {
    int lg = blockIdx.x;
    int l = lg / GC;
    __shared__ float sf[FH];
    sf[threadIdx.x] = feats[(size_t)lg * FH + threadIdx.x];
    __syncthreads();
    int c = threadIdx.x;
    if (c < CC) {
        const float* w = &fcW[(size_t)(l * CC + c) * FH];
        float a = fcb[l * CC + c];
#pragma unroll 8
        for (int h = 0; h < FH; h++) a += sf[h] * w[h];
        out[(size_t)lg * CC + c] = a;
    }
}

// ---------------------------------------------------------------------------
extern "C" void kernel_launch(void* const* d_in, const int* in_sizes, int n_in,
                              void* d_out, int out_size) {
    const float* x_user    = (const float*)d_in[0];
    const float* x_item    = (const float*)d_in[1];
    const int*   e_u2i     = (const int*)d_in[2];
    const int*   e_i2u     = (const int*)d_in[3];
    const int*   b_user    = (const int*)d_in[4];
    const int*   b_item    = (const int*)d_in[5];
    const float* Wrel_u2i  = (const float*)d_in[6];
    const float* Wroot_u2i = (const float*)d_in[7];
    const float* bias_u2i  = (const float*)d_in[8];
    const float* Wrel_i2u  = (const float*)d_in[9];
    const float* Wroot_i2u = (const float*)d_in[10];
    const float* bias_i2u  = (const float*)d_in[11];
    const float* bng_u     = (const float*)d_in[12];
    const float* bnb_u     = (const float*)d_in[13];
    const float* bng_i     = (const float*)d_in[14];
    const float* bnb_i     = (const float*)d_in[15];
    const float* fcW       = (const float*)d_in[16];
    const float* fcb       = (const float*)d_in[17];
    float* out = (float*)d_out;

    float* buf = nullptr;
    cudaGetSymbolAddress((void**)&buf, g_buf);
    int* deg = nullptr;
    cudaGetSymbolAddress((void**)&deg, g_deg);
    int* csr = nullptr;
    cudaGetSymbolAddress((void**)&csr, g_csr);
    unsigned* ctr_su = nullptr;
    cudaGetSymbolAddress((void**)&ctr_su, g_ctr_su);
    unsigned* ctr_si = nullptr;
    cudaGetSymbolAddress((void**)&ctr_si, g_ctr_si);

    cudaFuncSetAttribute(k_gemm_s, cudaFuncAttributeMaxDynamicSharedMemorySize, GSMEM);

    float* XU    = buf + OFF_XU;
    float* XI    = buf + OFF_XI;
    float* agg_u = buf + OFF_AGU;
    float* agg_i = buf + OFF_AGI;
    float* new_u = buf + OFF_NWU;
    float* new_i = buf + OFF_NWI;
    float* cnt   = buf + OFF_CNT;
    float* inv   = buf + OFF_INV;
    float* st_u  = buf + OFF_STATS;        // 256 floats
    float* st_i  = buf + OFF_STATS + 256;
    float* bn_u  = buf + OFF_BN;
    float* bn_i  = buf + OFF_BN + 256;

    int* deg_i = deg;                      // item-dst buckets (u2i)
    int* deg_u = deg + 50000;              // user-dst buckets (i2u)
    int* csr_i = csr;
    int* csr_u = csr + 50000ull * DEGCAP;

    const int OUT_ELEMS = LC * GC * CC + LC * GC * FH;
    const int OUT4 = OUT_ELEMS / 4;
    float* feats = out + LC * GC * CC;
    const int ZTOT = 25000 + OUT4 + 128 + 3200000;

    // lazy host resources (created on the uncaptured correctness call)
    static cudaStream_t s1 = nullptr;
    static cudaEvent_t evS = nullptr, evI[LC], evU[LC];
    if (!s1) {
        cudaStreamCreateWithFlags(&s1, cudaStreamNonBlocking);
        cudaEventCreateWithFlags(&evS, cudaEventDisableTiming);
        for (int l = 0; l < LC; l++) {
            cudaEventCreateWithFlags(&evI[l], cudaEventDisableTiming);
            cudaEventCreateWithFlags(&evU[l], cudaEventDisableTiming);
        }
    }

    const int GB = (50000 * 32 + 255) / 256;   // gather/apply grids per side

    // ---- setup on the capture (default) stream ----
    k_zeroall<<<(ZTOT + 255) / 256, 256>>>((float*)deg, out, OUT4, cnt,
                                           x_user, x_item, XU, XI);
    k_build2<<<(2 * EC + 255) / 256, 256>>>(e_u2i, e_i2u, deg, csr);
    k_count<<<64, 1024>>>(b_user, b_item, cnt, inv);
    cudaEventRecord(evS, 0);
    cudaStreamWaitEvent(s1, evS, 0);

    // Chains: stream0 = I-side (gather_i reads XU), s1 = U-side (gather_u reads XI)
    const float* srcU0 = x_user;   // layer-0 gathers read raw inputs
    const float* srcI0 = x_item;

    for (int l = 0; l < LC; l++) {
        size_t wo = (size_t)l * FH * FH;
        float* fl = feats + (size_t)l * GC * FH;

        // cross-chain waits (layer>0: I needs last apply_u, U needs last apply_i)
        if (l > 0) {
            cudaStreamWaitEvent(0, evU[l - 1], 0);
            cudaStreamWaitEvent(s1, evI[l - 1], 0);
        }

        // ---- I-side on stream 0 ----
        k_gather_s<<<GB, 256>>>(l == 0 ? srcU0 : XU, agg_i, deg_i, csr_i, st_i);
        k_gemm_s<<<NT, 256, GSMEM>>>(agg_i, XI, Wrel_u2i + wo, Wroot_u2i + wo,
                                     bias_u2i + l * FH, new_i);
        k_stats_s<<<NT, 128>>>(new_i, st_i, bn_i, bng_i, bnb_i, ctr_si);
        k_apply_s<<<GB, 256>>>(new_i, bn_i, b_item, inv, XI, fl);
        cudaEventRecord(evI[l], 0);

        // ---- U-side on stream 1 ----
        k_gather_s<<<GB, 256, 0, s1>>>(l == 0 ? srcI0 : XI, agg_u, deg_u, csr_u, st_u);
        k_gemm_s<<<NT, 256, GSMEM, s1>>>(agg_u, XU, Wrel_i2u + wo, Wroot_i2u + wo,
                                         bias_i2u + l * FH, new_u);
        k_stats_s<<<NT, 128, 0, s1>>>(new_u, st_u, bn_u, bng_u, bnb_u, ctr_su);
        k_apply_s<<<GB, 256, 0, s1>>>(new_u, bn_u, b_user, inv, XU, fl);
        cudaEventRecord(evU[l], s1);
    }

    // join U-chain into the capture stream, then finish
    cudaStreamWaitEvent(0, evU[LC - 1], 0);
    k_logits<<<LC * GC, FH>>>(feats, fcW, fcb, out);
}